// round 3
// baseline (speedup 1.0000x reference)
#include <cuda_runtime.h>
#include <math.h>

#define BB     2
#define NP     8192        // N*P
#define MM     16
#define BM     32          // BB*MM
#define CC     128
#define HH     256
#define NPAIR  (BB*NP*MM)  // 262144
#define TILE   16
#define TSTR   20          // padded tile stride (words) for [hidden][pair] smem
#define MLP_GRID 444       // 148 SMs * 3 blocks

// ---------------- scratch (device globals; no allocation) ----------------
__device__ float  g_cond[BM*HH];    // conditioning rows  (B*M, H)
__device__ float  g_R[BM*9];        // rotation matrices
__device__ int    g_count;          // number of inside pairs
__device__ int    g_idx[NPAIR];     // output index of each inside pair
__device__ float4 g_xt[NPAIR];      // Xt.xyz, w = bm as int bits

// ---------------- kernel 1: cond rows + rotations + counter reset ----------------
__global__ void k_init(const float* __restrict__ psf, const float* __restrict__ Wc,
                       const float* __restrict__ bc, const float* __restrict__ rot)
{
    int bm = blockIdx.x;       // 0..31
    int h  = threadIdx.x;      // 0..255
    __shared__ float sp[CC];
    if (h < CC) sp[h] = psf[bm*CC + h];
    __syncthreads();
    float acc = bc[h];
    #pragma unroll 8
    for (int c = 0; c < CC; ++c) acc += sp[c] * Wc[c*HH + h];
    g_cond[bm*HH + h] = acc;

    if (h == 0) {
        float w = rot[bm*4+0], x = rot[bm*4+1], y = rot[bm*4+2], z = rot[bm*4+3];
        float n = sqrtf(w*w + x*x + y*y + z*z);
        w /= n; x /= n; y /= n; z /= n;
        float* R = &g_R[bm*9];
        R[0] = 1.f - 2.f*(y*y + z*z); R[1] = 2.f*(x*y - w*z);       R[2] = 2.f*(x*z + w*y);
        R[3] = 2.f*(x*y + w*z);       R[4] = 1.f - 2.f*(x*x + z*z); R[5] = 2.f*(y*z - w*x);
        R[6] = 2.f*(x*z - w*y);       R[7] = 2.f*(y*z + w*x);       R[8] = 1.f - 2.f*(x*x + y*y);
        if (bm == 0) g_count = 0;
    }
}

// ---------------- kernel 2: mask + zero-fill + compaction ----------------
__global__ void k_mask(const float* __restrict__ pts, const float* __restrict__ trans,
                       const float* __restrict__ scale, float* __restrict__ out)
{
    __shared__ float sR[BM*9], sT[BM*3], sS[BM*3];
    int tid = threadIdx.x;
    for (int i = tid; i < BM*9; i += 256) sR[i] = g_R[i];   // BM*9 = 288 > 256: strided!
    if (tid < BM*3) { sT[tid] = trans[tid]; sS[tid] = scale[tid]; }
    __syncthreads();

    int idx = blockIdx.x * blockDim.x + tid;   // 0..16383 (B*Np)
    int b   = idx >> 13;                       // / 8192
    float px = pts[idx*3+0], py = pts[idx*3+1], pz = pts[idx*3+2];

    // zero-fill the 16 outputs of this point (inside pairs overwritten later)
    float4* o4 = reinterpret_cast<float4*>(out) + idx*4;
    float4 z4 = make_float4(0.f, 0.f, 0.f, 0.f);
    o4[0] = z4; o4[1] = z4; o4[2] = z4; o4[3] = z4;

    int lane = tid & 31;
    for (int m = 0; m < MM; ++m) {
        int bm = b*MM + m;
        float xc = px - sT[bm*3+0];
        float yc = py - sT[bm*3+1];
        float zc = pz - sT[bm*3+2];
        const float* R = &sR[bm*9];
        float xt = R[0]*xc + R[1]*yc + R[2]*zc;
        float yt = R[3]*xc + R[4]*yc + R[5]*zc;
        float zt = R[6]*xc + R[7]*yc + R[8]*zc;
        float fx = xt / sS[bm*3+0];
        float fy = yt / sS[bm*3+1];
        float fz = zt / sS[bm*3+2];
        float F  = fx*fx + fy*fy + fz*fz;
        bool inside = (F <= 1.0f);

        unsigned ballot = __ballot_sync(0xffffffffu, inside);
        int cnt = __popc(ballot);
        int base = 0;
        if (lane == 0 && cnt) base = atomicAdd(&g_count, cnt);
        base = __shfl_sync(0xffffffffu, base, 0);
        if (inside) {
            int pos = base + __popc(ballot & ((1u << lane) - 1u));
            g_idx[pos] = idx*MM + m;
            g_xt[pos]  = make_float4(xt, yt, zt, __int_as_float(bm));
        }
    }
}

// ---------------- kernel 3: fused MLP over compacted pairs ----------------
#define FMA16(W) do { \
    acc[0]  = fmaf(h0.x, (W), acc[0]);  acc[1]  = fmaf(h0.y, (W), acc[1]);  \
    acc[2]  = fmaf(h0.z, (W), acc[2]);  acc[3]  = fmaf(h0.w, (W), acc[3]);  \
    acc[4]  = fmaf(h1.x, (W), acc[4]);  acc[5]  = fmaf(h1.y, (W), acc[5]);  \
    acc[6]  = fmaf(h1.z, (W), acc[6]);  acc[7]  = fmaf(h1.w, (W), acc[7]);  \
    acc[8]  = fmaf(h2.x, (W), acc[8]);  acc[9]  = fmaf(h2.y, (W), acc[9]);  \
    acc[10] = fmaf(h2.z, (W), acc[10]); acc[11] = fmaf(h2.w, (W), acc[11]); \
    acc[12] = fmaf(h3.x, (W), acc[12]); acc[13] = fmaf(h3.y, (W), acc[13]); \
    acc[14] = fmaf(h3.z, (W), acc[14]); acc[15] = fmaf(h3.w, (W), acc[15]); \
} while (0)

__global__ void __launch_bounds__(256, 3) k_mlp(
    const float* __restrict__ Wp, const float* __restrict__ bp,
    const float* __restrict__ W1, const float* __restrict__ b1,
    const float* __restrict__ W2, const float* __restrict__ b2,
    const float* __restrict__ Wout, const float* __restrict__ bout,
    float* __restrict__ out)
{
    int total = g_count;

    __shared__ float sA[TILE*HH];                    // net0, [t][j] layout  (16 KB)
    __shared__ __align__(16) float sH[HH*TSTR];      // relu acts, [i][t]    (20 KB)
    __shared__ float4 sXT[TILE];
    __shared__ int    sIdx[TILE];
    __shared__ float  sRed[8*TILE];

    int j    = threadIdx.x;   // hidden column
    int lane = j & 31, wid = j >> 5;

    float wp0 = Wp[0*HH + j], wp1 = Wp[1*HH + j], wp2 = Wp[2*HH + j];
    float bpj = bp[j], b1j = b1[j], b2j = b2[j], wOj = Wout[j];
    float bo  = bout[0];

    for (int base = blockIdx.x * TILE; base < total; base += MLP_GRID * TILE) {
        int nt = min(TILE, total - base);
        __syncthreads();                     // protect sXT/sIdx/sRed reuse
        if (j < TILE) {
            if (j < nt) { sXT[j] = g_xt[base + j]; sIdx[j] = g_idx[base + j]; }
            else        { sXT[j] = make_float4(0.f,0.f,0.f,__int_as_float(0)); sIdx[j] = -1; }
        }
        __syncthreads();

        float acc[TILE];

        // ---- phase 1: net0 = Xt@Wp + bp + cond ----
        #pragma unroll
        for (int t = 0; t < TILE; ++t) {
            float4 xt = sXT[t];
            int bm = __float_as_int(xt.w);
            float v = fmaf(wp0, xt.x, fmaf(wp1, xt.y, fmaf(wp2, xt.z,
                      bpj + __ldg(&g_cond[bm*HH + j]))));
            sA[t*HH + j] = v;
            acc[t] = fmaxf(v, 0.f);
        }
        #pragma unroll
        for (int t = 0; t < TILE; t += 4)
            *reinterpret_cast<float4*>(&sH[j*TSTR + t]) =
                make_float4(acc[t], acc[t+1], acc[t+2], acc[t+3]);
        __syncthreads();

        // ---- layer 1: t1 = relu(net0)@W1 + b1 ----
        #pragma unroll
        for (int t = 0; t < TILE; ++t) acc[t] = b1j;
        #pragma unroll 4
        for (int i = 0; i < HH; ++i) {
            float w = W1[i*HH + j];
            const float4* hp = reinterpret_cast<const float4*>(&sH[i*TSTR]);
            float4 h0 = hp[0], h1 = hp[1], h2 = hp[2], h3 = hp[3];
            FMA16(w);
        }
        __syncthreads();
        #pragma unroll
        for (int t = 0; t < TILE; t += 4)
            *reinterpret_cast<float4*>(&sH[j*TSTR + t]) =
                make_float4(fmaxf(acc[t],0.f), fmaxf(acc[t+1],0.f),
                            fmaxf(acc[t+2],0.f), fmaxf(acc[t+3],0.f));
        __syncthreads();

        // ---- layer 2: t2 = relu(t1)@W2 + b2 ; net = net0 + t2 ----
        #pragma unroll
        for (int t = 0; t < TILE; ++t) acc[t] = b2j;
        #pragma unroll 4
        for (int i = 0; i < HH; ++i) {
            float w = W2[i*HH + j];
            const float4* hp = reinterpret_cast<const float4*>(&sH[i*TSTR]);
            float4 h0 = hp[0], h1 = hp[1], h2 = hp[2], h3 = hp[3];
            FMA16(w);
        }

        // ---- occ partials: relu(net)*Wout[j], reduce over j ----
        #pragma unroll
        for (int t = 0; t < TILE; ++t) {
            float v = sA[t*HH + j] + acc[t];
            acc[t] = fmaxf(v, 0.f) * wOj;
        }
        #pragma unroll
        for (int t = 0; t < TILE; ++t) {
            float s = acc[t];
            s += __shfl_xor_sync(0xffffffffu, s, 16);
            s += __shfl_xor_sync(0xffffffffu, s, 8);
            s += __shfl_xor_sync(0xffffffffu, s, 4);
            s += __shfl_xor_sync(0xffffffffu, s, 2);
            s += __shfl_xor_sync(0xffffffffu, s, 1);
            if (lane == 0) sRed[wid*TILE + t] = s;
        }
        __syncthreads();
        if (j < TILE) {
            float s = 0.f;
            #pragma unroll
            for (int w = 0; w < 8; ++w) s += sRed[w*TILE + j];
            int oidx = sIdx[j];
            if (oidx >= 0) {
                float occ = s + bo;
                out[oidx] = 1.0f / (1.0f + expf(-10.0f * occ));
            }
        }
    }
}

// ---------------- launcher ----------------
extern "C" void kernel_launch(void* const* d_in, const int* in_sizes, int n_in,
                              void* d_out, int out_size)
{
    const float* ray   = (const float*)d_in[0];
    const float* trans = (const float*)d_in[1];
    const float* rot   = (const float*)d_in[2];
    const float* scl   = (const float*)d_in[3];
    const float* psf   = (const float*)d_in[4];
    const float* Wp    = (const float*)d_in[5];
    const float* bp    = (const float*)d_in[6];
    const float* Wc    = (const float*)d_in[7];
    const float* bc    = (const float*)d_in[8];
    const float* W1    = (const float*)d_in[9];
    const float* b1    = (const float*)d_in[10];
    const float* W2    = (const float*)d_in[11];
    const float* b2    = (const float*)d_in[12];
    const float* Wout  = (const float*)d_in[13];
    const float* bout  = (const float*)d_in[14];
    float* out = (float*)d_out;

    k_init<<<BM, HH>>>(psf, Wc, bc, rot);
    k_mask<<<(BB*NP)/256, 256>>>(ray, trans, scl, out);
    k_mlp<<<MLP_GRID, 256>>>(Wp, bp, W1, b1, W2, b2, Wout, bout, out);
}

// round 4
// speedup vs baseline: 1.0976x; 1.0976x over previous
#include <cuda_runtime.h>
#include <math.h>

#define BB     2
#define NP     8192        // N*P
#define MM     16
#define BM     32          // BB*MM
#define CC     128
#define HH     256
#define NPAIR  (BB*NP*MM)  // 262144
#define TILE   16
#define TSTR   20          // padded tile stride (words) for [hidden][pair] smem
#define MLP_GRID 444       // 148 SMs * 3 blocks

// ---------------- scratch (device globals; no allocation) ----------------
__device__ float  g_cond[BM*HH];    // conditioning rows  (B*M, H)
__device__ int    g_count;          // number of inside pairs
__device__ int    g_idx[NPAIR];     // output index of each inside pair
__device__ float4 g_xt[NPAIR];      // Xt.xyz, w = bm as int bits

// ---------------- f32x2 packed helpers (sm_103a) ----------------
__device__ __forceinline__ void ffma2(unsigned long long& d,
                                      unsigned long long h, unsigned long long w) {
    asm("fma.rn.f32x2 %0, %1, %2, %0;" : "+l"(d) : "l"(h), "l"(w));
}
__device__ __forceinline__ unsigned long long splat2(float w) {
    unsigned long long r;
    asm("mov.b64 %0, {%1, %1};" : "=l"(r) : "r"(__float_as_uint(w)));
    return r;
}
__device__ __forceinline__ float2 unpack2(unsigned long long v) {
    unsigned lo, hi;
    asm("mov.b64 {%0, %1}, %2;" : "=r"(lo), "=r"(hi) : "l"(v));
    return make_float2(__uint_as_float(lo), __uint_as_float(hi));
}

// ---------------- kernel 1: cond rows + counter reset ----------------
__global__ void k_init(const float* __restrict__ psf, const float* __restrict__ Wc,
                       const float* __restrict__ bc)
{
    int bm = blockIdx.x;       // 0..31
    int h  = threadIdx.x;      // 0..255
    __shared__ float sp[CC];
    if (h < CC) sp[h] = psf[bm*CC + h];
    __syncthreads();

    // 8 independent accumulators -> 8 LDG chains in flight per unroll body
    float a0=0.f,a1=0.f,a2=0.f,a3=0.f,a4=0.f,a5=0.f,a6=0.f,a7=0.f;
    #pragma unroll 4
    for (int c = 0; c < CC; c += 8) {
        a0 = fmaf(sp[c+0], Wc[(c+0)*HH + h], a0);
        a1 = fmaf(sp[c+1], Wc[(c+1)*HH + h], a1);
        a2 = fmaf(sp[c+2], Wc[(c+2)*HH + h], a2);
        a3 = fmaf(sp[c+3], Wc[(c+3)*HH + h], a3);
        a4 = fmaf(sp[c+4], Wc[(c+4)*HH + h], a4);
        a5 = fmaf(sp[c+5], Wc[(c+5)*HH + h], a5);
        a6 = fmaf(sp[c+6], Wc[(c+6)*HH + h], a6);
        a7 = fmaf(sp[c+7], Wc[(c+7)*HH + h], a7);
    }
    g_cond[bm*HH + h] = bc[h] + ((a0+a1)+(a2+a3)) + ((a4+a5)+(a6+a7));

    if (bm == 0 && h == 0) g_count = 0;
}

// ---------------- kernel 2: mask + zero-fill + compaction ----------------
__global__ void k_mask(const float* __restrict__ pts, const float* __restrict__ trans,
                       const float* __restrict__ rot, const float* __restrict__ scale,
                       float* __restrict__ out)
{
    __shared__ float sR[BM*9], sT[BM*3], sS[BM*3];
    int tid = threadIdx.x;
    if (tid < BM) {            // each of 32 threads builds one rotation matrix
        float w = rot[tid*4+0], x = rot[tid*4+1], y = rot[tid*4+2], z = rot[tid*4+3];
        float n = rsqrtf(w*w + x*x + y*y + z*z);
        w *= n; x *= n; y *= n; z *= n;
        float* R = &sR[tid*9];
        R[0] = 1.f - 2.f*(y*y + z*z); R[1] = 2.f*(x*y - w*z);       R[2] = 2.f*(x*z + w*y);
        R[3] = 2.f*(x*y + w*z);       R[4] = 1.f - 2.f*(x*x + z*z); R[5] = 2.f*(y*z - w*x);
        R[6] = 2.f*(x*z - w*y);       R[7] = 2.f*(y*z + w*x);       R[8] = 1.f - 2.f*(x*x + y*y);
    }
    if (tid < BM*3) { sT[tid] = trans[tid]; sS[tid] = scale[tid]; }
    __syncthreads();

    int idx = blockIdx.x * blockDim.x + tid;   // 0..16383 (B*Np)
    int b   = idx >> 13;                       // / 8192
    float px = pts[idx*3+0], py = pts[idx*3+1], pz = pts[idx*3+2];

    // zero-fill the 16 outputs of this point (inside pairs overwritten later)
    float4* o4 = reinterpret_cast<float4*>(out) + idx*4;
    float4 z4 = make_float4(0.f, 0.f, 0.f, 0.f);
    o4[0] = z4; o4[1] = z4; o4[2] = z4; o4[3] = z4;

    int lane = tid & 31;
    for (int m = 0; m < MM; ++m) {
        int bm = b*MM + m;
        float xc = px - sT[bm*3+0];
        float yc = py - sT[bm*3+1];
        float zc = pz - sT[bm*3+2];
        const float* R = &sR[bm*9];
        float xt = R[0]*xc + R[1]*yc + R[2]*zc;
        float yt = R[3]*xc + R[4]*yc + R[5]*zc;
        float zt = R[6]*xc + R[7]*yc + R[8]*zc;
        float fx = xt / sS[bm*3+0];
        float fy = yt / sS[bm*3+1];
        float fz = zt / sS[bm*3+2];
        float F  = fx*fx + fy*fy + fz*fz;
        bool inside = (F <= 1.0f);

        unsigned ballot = __ballot_sync(0xffffffffu, inside);
        int cnt = __popc(ballot);
        int base = 0;
        if (lane == 0 && cnt) base = atomicAdd(&g_count, cnt);
        base = __shfl_sync(0xffffffffu, base, 0);
        if (inside) {
            int pos = base + __popc(ballot & ((1u << lane) - 1u));
            g_idx[pos] = idx*MM + m;
            g_xt[pos]  = make_float4(xt, yt, zt, __int_as_float(bm));
        }
    }
}

// ---------------- kernel 3: fused MLP over compacted pairs (f32x2) ----------------
__global__ void __launch_bounds__(256, 3) k_mlp(
    const float* __restrict__ Wp, const float* __restrict__ bp,
    const float* __restrict__ W1, const float* __restrict__ b1,
    const float* __restrict__ W2, const float* __restrict__ b2,
    const float* __restrict__ Wout, const float* __restrict__ bout,
    float* __restrict__ out)
{
    int total = g_count;

    __shared__ float sA[TILE*HH];                    // net0, [t][j] layout  (16 KB)
    __shared__ __align__(16) float sH[HH*TSTR];      // relu acts, [i][t]    (20 KB)
    __shared__ float4 sXT[TILE];
    __shared__ int    sIdx[TILE];
    __shared__ float  sRed[8*TILE];

    int j    = threadIdx.x;   // hidden column
    int lane = j & 31, wid = j >> 5;

    float wp0 = Wp[0*HH + j], wp1 = Wp[1*HH + j], wp2 = Wp[2*HH + j];
    float bpj = bp[j], b1j = b1[j], b2j = b2[j], wOj = Wout[j];
    float bo  = bout[0];

    for (int base = blockIdx.x * TILE; base < total; base += MLP_GRID * TILE) {
        int nt = min(TILE, total - base);
        __syncthreads();                     // protect sXT/sIdx/sRed reuse
        if (j < TILE) {
            if (j < nt) { sXT[j] = g_xt[base + j]; sIdx[j] = g_idx[base + j]; }
            else        { sXT[j] = make_float4(0.f,0.f,0.f,__int_as_float(0)); sIdx[j] = -1; }
        }
        __syncthreads();

        float a[TILE];                       // scalar view of the 16 pair values
        unsigned long long acc2[TILE/2];     // packed f32x2 accumulators

        // ---- phase 1: net0 = Xt@Wp + bp + cond ----
        #pragma unroll
        for (int t = 0; t < TILE; ++t) {
            float4 xt = sXT[t];
            int bm = __float_as_int(xt.w);
            float v = fmaf(wp0, xt.x, fmaf(wp1, xt.y, fmaf(wp2, xt.z,
                      bpj + __ldg(&g_cond[bm*HH + j]))));
            sA[t*HH + j] = v;
            a[t] = fmaxf(v, 0.f);
        }
        #pragma unroll
        for (int t = 0; t < TILE; t += 4)
            *reinterpret_cast<float4*>(&sH[j*TSTR + t]) =
                make_float4(a[t], a[t+1], a[t+2], a[t+3]);
        __syncthreads();

        // ---- layer 1: t1 = relu(net0)@W1 + b1 ----
        {
            unsigned long long binit = splat2(b1j);
            #pragma unroll
            for (int k = 0; k < TILE/2; ++k) acc2[k] = binit;
            #pragma unroll 4
            for (int i = 0; i < HH; ++i) {
                unsigned long long wpk = splat2(W1[i*HH + j]);
                const ulonglong2* hp = reinterpret_cast<const ulonglong2*>(&sH[i*TSTR]);
                ulonglong2 q0 = hp[0], q1 = hp[1], q2 = hp[2], q3 = hp[3];
                ffma2(acc2[0], q0.x, wpk); ffma2(acc2[1], q0.y, wpk);
                ffma2(acc2[2], q1.x, wpk); ffma2(acc2[3], q1.y, wpk);
                ffma2(acc2[4], q2.x, wpk); ffma2(acc2[5], q2.y, wpk);
                ffma2(acc2[6], q3.x, wpk); ffma2(acc2[7], q3.y, wpk);
            }
        }
        #pragma unroll
        for (int k = 0; k < TILE/2; ++k) {
            float2 v = unpack2(acc2[k]);
            a[2*k]   = fmaxf(v.x, 0.f);
            a[2*k+1] = fmaxf(v.y, 0.f);
        }
        __syncthreads();
        #pragma unroll
        for (int t = 0; t < TILE; t += 4)
            *reinterpret_cast<float4*>(&sH[j*TSTR + t]) =
                make_float4(a[t], a[t+1], a[t+2], a[t+3]);
        __syncthreads();

        // ---- layer 2: t2 = relu(t1)@W2 + b2 ; net = net0 + t2 ----
        {
            unsigned long long binit = splat2(b2j);
            #pragma unroll
            for (int k = 0; k < TILE/2; ++k) acc2[k] = binit;
            #pragma unroll 4
            for (int i = 0; i < HH; ++i) {
                unsigned long long wpk = splat2(W2[i*HH + j]);
                const ulonglong2* hp = reinterpret_cast<const ulonglong2*>(&sH[i*TSTR]);
                ulonglong2 q0 = hp[0], q1 = hp[1], q2 = hp[2], q3 = hp[3];
                ffma2(acc2[0], q0.x, wpk); ffma2(acc2[1], q0.y, wpk);
                ffma2(acc2[2], q1.x, wpk); ffma2(acc2[3], q1.y, wpk);
                ffma2(acc2[4], q2.x, wpk); ffma2(acc2[5], q2.y, wpk);
                ffma2(acc2[6], q3.x, wpk); ffma2(acc2[7], q3.y, wpk);
            }
        }

        // ---- occ partials: relu(net0 + t2)*Wout[j], reduce over j ----
        #pragma unroll
        for (int k = 0; k < TILE/2; ++k) {
            float2 v = unpack2(acc2[k]);
            a[2*k]   = fmaxf(sA[(2*k)*HH + j]   + v.x, 0.f) * wOj;
            a[2*k+1] = fmaxf(sA[(2*k+1)*HH + j] + v.y, 0.f) * wOj;
        }
        #pragma unroll
        for (int t = 0; t < TILE; ++t) {
            float s = a[t];
            s += __shfl_xor_sync(0xffffffffu, s, 16);
            s += __shfl_xor_sync(0xffffffffu, s, 8);
            s += __shfl_xor_sync(0xffffffffu, s, 4);
            s += __shfl_xor_sync(0xffffffffu, s, 2);
            s += __shfl_xor_sync(0xffffffffu, s, 1);
            if (lane == 0) sRed[wid*TILE + t] = s;
        }
        __syncthreads();
        if (j < TILE) {
            float s = 0.f;
            #pragma unroll
            for (int w = 0; w < 8; ++w) s += sRed[w*TILE + j];
            int oidx = sIdx[j];
            if (oidx >= 0) {
                float occ = s + bo;
                out[oidx] = 1.0f / (1.0f + expf(-10.0f * occ));
            }
        }
    }
}

// ---------------- launcher ----------------
extern "C" void kernel_launch(void* const* d_in, const int* in_sizes, int n_in,
                              void* d_out, int out_size)
{
    const float* ray   = (const float*)d_in[0];
    const float* trans = (const float*)d_in[1];
    const float* rot   = (const float*)d_in[2];
    const float* scl   = (const float*)d_in[3];
    const float* psf   = (const float*)d_in[4];
    const float* Wp    = (const float*)d_in[5];
    const float* bp    = (const float*)d_in[6];
    const float* Wc    = (const float*)d_in[7];
    const float* bc    = (const float*)d_in[8];
    const float* W1    = (const float*)d_in[9];
    const float* b1    = (const float*)d_in[10];
    const float* W2    = (const float*)d_in[11];
    const float* b2    = (const float*)d_in[12];
    const float* Wout  = (const float*)d_in[13];
    const float* bout  = (const float*)d_in[14];
    float* out = (float*)d_out;

    k_init<<<BM, HH>>>(psf, Wc, bc);
    k_mask<<<(BB*NP)/256, 256>>>(ray, trans, rot, scl, out);
    k_mlp<<<MLP_GRID, 256>>>(Wp, bp, W1, b1, W2, b2, Wout, bout, out);
}

// round 5
// speedup vs baseline: 1.4734x; 1.3424x over previous
#include <cuda_runtime.h>
#include <math.h>

#define BB     2
#define NP     8192        // N*P
#define MM     16
#define BM     32          // BB*MM
#define CC     128
#define HH     256
#define NPAIR  (BB*NP*MM)  // 262144
#define TILE   32
#define TSTR   36          // padded row stride (floats) for sH [i][t]
#define MLP_GRID 444       // 148 SMs * 3 (resident 2/SM; grid-stride safe)

// ---------------- scratch (device globals; no allocation) ----------------
__device__ float  g_cond[BM*HH];    // conditioning rows  (B*M, H)
__device__ int    g_count;          // number of inside pairs
__device__ int    g_idx[NPAIR];     // output index of each inside pair
__device__ float4 g_xt[NPAIR];      // Xt.xyz, w = bm as int bits

// ---------------- f32x2 packed helpers (sm_103a) ----------------
__device__ __forceinline__ void ffma2(unsigned long long& d,
                                      unsigned long long h, unsigned long long w) {
    asm("fma.rn.f32x2 %0, %1, %2, %0;" : "+l"(d) : "l"(h), "l"(w));
}
__device__ __forceinline__ unsigned long long splat2(float w) {
    unsigned long long r;
    asm("mov.b64 %0, {%1, %1};" : "=l"(r) : "r"(__float_as_uint(w)));
    return r;
}
__device__ __forceinline__ float2 unpack2(unsigned long long v) {
    unsigned lo, hi;
    asm("mov.b64 {%0, %1}, %2;" : "=r"(lo), "=r"(hi) : "l"(v));
    return make_float2(__uint_as_float(lo), __uint_as_float(hi));
}

// ---------------- kernel 1: cond rows + counter reset ----------------
// grid 128 = 32 bm * 4 chunks of 64 hidden cols; block 64 threads
__global__ void k_prep(const float* __restrict__ psf, const float* __restrict__ Wc,
                       const float* __restrict__ bc)
{
    int bm = blockIdx.x >> 2;
    int j  = ((blockIdx.x & 3) << 6) + threadIdx.x;
    __shared__ float sp[CC];
    sp[threadIdx.x]      = psf[bm*CC + threadIdx.x];
    sp[threadIdx.x + 64] = psf[bm*CC + threadIdx.x + 64];
    __syncthreads();

    float a0=0.f,a1=0.f,a2=0.f,a3=0.f,a4=0.f,a5=0.f,a6=0.f,a7=0.f;
    #pragma unroll 4
    for (int c = 0; c < CC; c += 8) {
        a0 = fmaf(sp[c+0], Wc[(c+0)*HH + j], a0);
        a1 = fmaf(sp[c+1], Wc[(c+1)*HH + j], a1);
        a2 = fmaf(sp[c+2], Wc[(c+2)*HH + j], a2);
        a3 = fmaf(sp[c+3], Wc[(c+3)*HH + j], a3);
        a4 = fmaf(sp[c+4], Wc[(c+4)*HH + j], a4);
        a5 = fmaf(sp[c+5], Wc[(c+5)*HH + j], a5);
        a6 = fmaf(sp[c+6], Wc[(c+6)*HH + j], a6);
        a7 = fmaf(sp[c+7], Wc[(c+7)*HH + j], a7);
    }
    g_cond[bm*HH + j] = bc[j] + ((a0+a1)+(a2+a3)) + ((a4+a5)+(a6+a7));

    if (blockIdx.x == 0 && threadIdx.x == 0) g_count = 0;
}

// ---------------- kernel 2: mask + zero-fill + block-scan compaction ----------------
// grid 128, block 128 (one point per thread)
__global__ void k_mask(const float* __restrict__ pts, const float* __restrict__ trans,
                       const float* __restrict__ rot, const float* __restrict__ scale,
                       float* __restrict__ out)
{
    __shared__ float sR[BM*9], sT[BM*3], sS[BM*3];
    __shared__ int   sWarp[4], sBase;
    int tid = threadIdx.x;
    if (tid < BM) {
        float w = rot[tid*4+0], x = rot[tid*4+1], y = rot[tid*4+2], z = rot[tid*4+3];
        float n = rsqrtf(w*w + x*x + y*y + z*z);
        w *= n; x *= n; y *= n; z *= n;
        float* R = &sR[tid*9];
        R[0] = 1.f - 2.f*(y*y + z*z); R[1] = 2.f*(x*y - w*z);       R[2] = 2.f*(x*z + w*y);
        R[3] = 2.f*(x*y + w*z);       R[4] = 1.f - 2.f*(x*x + z*z); R[5] = 2.f*(y*z - w*x);
        R[6] = 2.f*(x*z - w*y);       R[7] = 2.f*(y*z + w*x);       R[8] = 1.f - 2.f*(x*x + y*y);
    }
    if (tid < BM*3) { sT[tid] = trans[tid]; sS[tid] = scale[tid]; }
    __syncthreads();

    int idx = blockIdx.x * 128 + tid;          // 0..16383
    int b   = idx >> 13;
    float px = pts[idx*3+0], py = pts[idx*3+1], pz = pts[idx*3+2];

    // zero-fill this point's 16 outputs
    float4* o4 = reinterpret_cast<float4*>(out) + idx*4;
    float4 z4 = make_float4(0.f, 0.f, 0.f, 0.f);
    o4[0] = z4; o4[1] = z4; o4[2] = z4; o4[3] = z4;

    // pass 1: mask bits
    unsigned maskbits = 0;
    #pragma unroll
    for (int m = 0; m < MM; ++m) {
        int bm = b*MM + m;
        float xc = px - sT[bm*3+0], yc = py - sT[bm*3+1], zc = pz - sT[bm*3+2];
        const float* R = &sR[bm*9];
        float xt = R[0]*xc + R[1]*yc + R[2]*zc;
        float yt = R[3]*xc + R[4]*yc + R[5]*zc;
        float zt = R[6]*xc + R[7]*yc + R[8]*zc;
        float fx = xt / sS[bm*3+0], fy = yt / sS[bm*3+1], fz = zt / sS[bm*3+2];
        if (fx*fx + fy*fy + fz*fz <= 1.0f) maskbits |= (1u << m);
    }

    // block scan of per-thread counts, one global atomic per block
    int cnt  = __popc(maskbits);
    int lane = tid & 31, wid = tid >> 5;
    int incl = cnt;
    #pragma unroll
    for (int d = 1; d < 32; d <<= 1) {
        int v = __shfl_up_sync(0xffffffffu, incl, d);
        if (lane >= d) incl += v;
    }
    if (lane == 31) sWarp[wid] = incl;
    __syncthreads();
    if (tid == 0) {
        int s = 0;
        #pragma unroll
        for (int w = 0; w < 4; ++w) { int t = sWarp[w]; sWarp[w] = s; s += t; }
        sBase = s ? atomicAdd(&g_count, s) : 0;
    }
    __syncthreads();
    int off = sBase + sWarp[wid] + (incl - cnt);

    // pass 2: recompute Xt for inside m's and write compacted
    unsigned mb = maskbits;
    while (mb) {
        int m = __ffs(mb) - 1; mb &= mb - 1;
        int bm = b*MM + m;
        float xc = px - sT[bm*3+0], yc = py - sT[bm*3+1], zc = pz - sT[bm*3+2];
        const float* R = &sR[bm*9];
        float xt = R[0]*xc + R[1]*yc + R[2]*zc;
        float yt = R[3]*xc + R[4]*yc + R[5]*zc;
        float zt = R[6]*xc + R[7]*yc + R[8]*zc;
        g_idx[off] = idx*MM + m;
        g_xt[off]  = make_float4(xt, yt, zt, __int_as_float(bm));
        ++off;
    }
}

// ---------------- kernel 3: fused MLP, TILE=32, f32x2, pipelined weights ----------------
#define LAYER_LOOP(Wm)                                                            \
    {                                                                             \
        const float* wp_ = (Wm) + j;                                              \
        float wcur[8];                                                            \
        _Pragma("unroll")                                                         \
        for (int u = 0; u < 8; ++u) wcur[u] = wp_[u*HH];                          \
        for (int ib = 0; ib < HH; ib += 8) {                                      \
            float wnxt[8];                                                        \
            if (ib + 8 < HH) {                                                    \
                _Pragma("unroll")                                                 \
                for (int u = 0; u < 8; ++u) wnxt[u] = wp_[(ib+8+u)*HH];           \
            }                                                                     \
            _Pragma("unroll")                                                     \
            for (int u = 0; u < 8; ++u) {                                         \
                unsigned long long w2 = splat2(wcur[u]);                          \
                const ulonglong2* hp =                                            \
                    reinterpret_cast<const ulonglong2*>(&sH[(ib+u)*TSTR]);        \
                _Pragma("unroll")                                                 \
                for (int k = 0; k < 8; ++k) {                                     \
                    ulonglong2 q = hp[k];                                         \
                    ffma2(acc2[2*k],   q.x, w2);                                  \
                    ffma2(acc2[2*k+1], q.y, w2);                                  \
                }                                                                 \
            }                                                                     \
            _Pragma("unroll")                                                     \
            for (int u = 0; u < 8; ++u) wcur[u] = wnxt[u];                        \
        }                                                                         \
    }

__global__ void __launch_bounds__(256, 2) k_mlp(
    const float* __restrict__ Wp, const float* __restrict__ bp,
    const float* __restrict__ W1, const float* __restrict__ b1,
    const float* __restrict__ W2, const float* __restrict__ b2,
    const float* __restrict__ Wout, const float* __restrict__ bout,
    float* __restrict__ out)
{
    int total = g_count;

    __shared__ __align__(16) float sH[HH*TSTR];   // relu acts, [i][t]  (36.9 KB)
    __shared__ float4 sXT[TILE];
    __shared__ int    sIdx[TILE];
    __shared__ float  sRed[8*TILE];

    int j    = threadIdx.x;   // hidden column
    int lane = j & 31, wid = j >> 5;

    float wp0 = Wp[0*HH + j], wp1 = Wp[1*HH + j], wp2 = Wp[2*HH + j];
    float bpj = bp[j], b1j = b1[j], b2j = b2[j], wOj = Wout[j];
    float bo  = bout[0];

    for (int base = blockIdx.x * TILE; base < total; base += MLP_GRID * TILE) {
        int nt = min(TILE, total - base);
        __syncthreads();                          // protect sXT/sIdx/sRed/sH reuse
        if (j < TILE) {
            if (j < nt) { sXT[j] = g_xt[base + j]; sIdx[j] = g_idx[base + j]; }
            else        { sXT[j] = make_float4(0.f,0.f,0.f,__int_as_float(0)); sIdx[j] = -1; }
        }
        __syncthreads();

        unsigned long long acc2[TILE/2];

        // ---- phase 1: relu(net0) -> sH row j ----
        {
            float v[TILE];
            #pragma unroll
            for (int t = 0; t < TILE; ++t) {
                float4 xt = sXT[t];
                int bm = __float_as_int(xt.w);
                float n0 = fmaf(wp0, xt.x, fmaf(wp1, xt.y, fmaf(wp2, xt.z,
                           bpj + __ldg(&g_cond[bm*HH + j]))));
                v[t] = fmaxf(n0, 0.f);
            }
            #pragma unroll
            for (int t = 0; t < TILE; t += 4)
                *reinterpret_cast<float4*>(&sH[j*TSTR + t]) =
                    make_float4(v[t], v[t+1], v[t+2], v[t+3]);
        }
        __syncthreads();

        // ---- layer 1 ----
        {
            unsigned long long binit = splat2(b1j);
            #pragma unroll
            for (int k = 0; k < TILE/2; ++k) acc2[k] = binit;
            LAYER_LOOP(W1);
        }
        __syncthreads();                          // readers of sH done
        {
            float v[TILE];
            #pragma unroll
            for (int k = 0; k < TILE/2; ++k) {
                float2 p = unpack2(acc2[k]);
                v[2*k]   = fmaxf(p.x, 0.f);
                v[2*k+1] = fmaxf(p.y, 0.f);
            }
            #pragma unroll
            for (int t = 0; t < TILE; t += 4)
                *reinterpret_cast<float4*>(&sH[j*TSTR + t]) =
                    make_float4(v[t], v[t+1], v[t+2], v[t+3]);
        }
        __syncthreads();

        // ---- layer 2 ----
        {
            unsigned long long binit = splat2(b2j);
            #pragma unroll
            for (int k = 0; k < TILE/2; ++k) acc2[k] = binit;
            LAYER_LOOP(W2);
        }

        // ---- occ partials: relu(net0(recomputed) + t2) * Wout[j] ----
        float a[TILE];
        #pragma unroll
        for (int t = 0; t < TILE; ++t) {
            float4 xt = sXT[t];
            int bm = __float_as_int(xt.w);
            float n0 = fmaf(wp0, xt.x, fmaf(wp1, xt.y, fmaf(wp2, xt.z,
                       bpj + __ldg(&g_cond[bm*HH + j]))));
            float2 p = unpack2(acc2[t>>1]);
            float dx = (t & 1) ? p.y : p.x;
            a[t] = fmaxf(n0 + dx, 0.f) * wOj;
        }
        #pragma unroll
        for (int t = 0; t < TILE; ++t) {
            float s = a[t];
            s += __shfl_xor_sync(0xffffffffu, s, 16);
            s += __shfl_xor_sync(0xffffffffu, s, 8);
            s += __shfl_xor_sync(0xffffffffu, s, 4);
            s += __shfl_xor_sync(0xffffffffu, s, 2);
            s += __shfl_xor_sync(0xffffffffu, s, 1);
            if (lane == 0) sRed[wid*TILE + t] = s;
        }
        __syncthreads();
        if (j < TILE) {
            float s = 0.f;
            #pragma unroll
            for (int w = 0; w < 8; ++w) s += sRed[w*TILE + j];
            int oidx = sIdx[j];
            if (oidx >= 0) {
                float occ = s + bo;
                out[oidx] = 1.0f / (1.0f + expf(-10.0f * occ));
            }
        }
    }
}

// ---------------- launcher ----------------
extern "C" void kernel_launch(void* const* d_in, const int* in_sizes, int n_in,
                              void* d_out, int out_size)
{
    const float* ray   = (const float*)d_in[0];
    const float* trans = (const float*)d_in[1];
    const float* rot   = (const float*)d_in[2];
    const float* scl   = (const float*)d_in[3];
    const float* psf   = (const float*)d_in[4];
    const float* Wp    = (const float*)d_in[5];
    const float* bp    = (const float*)d_in[6];
    const float* Wc    = (const float*)d_in[7];
    const float* bc    = (const float*)d_in[8];
    const float* W1    = (const float*)d_in[9];
    const float* b1    = (const float*)d_in[10];
    const float* W2    = (const float*)d_in[11];
    const float* b2    = (const float*)d_in[12];
    const float* Wout  = (const float*)d_in[13];
    const float* bout  = (const float*)d_in[14];
    float* out = (float*)d_out;

    k_prep<<<128, 64>>>(psf, Wc, bc);
    k_mask<<<128, 128>>>(ray, trans, rot, scl, out);
    k_mlp<<<MLP_GRID, 256>>>(Wp, bp, W1, b1, W2, b2, Wout, bout, out);
}